// round 1
// baseline (speedup 1.0000x reference)
#include <cuda_runtime.h>

// 3x3 median blur, zero padding, fp32 NCHW (8,3,512,512).
// Each thread: 4 adjacent x-pixels (float4 load/store), Smith 19-CE median-of-9.

#define S2(a, b) { float _t = fminf(a, b); (b) = fmaxf(a, b); (a) = _t; }

__device__ __forceinline__ float median9(float p0, float p1, float p2,
                                         float p3, float p4, float p5,
                                         float p6, float p7, float p8) {
    // Smith (1996) median-of-9 sorting network: 19 compare-exchanges.
    S2(p1, p2); S2(p4, p5); S2(p7, p8);
    S2(p0, p1); S2(p3, p4); S2(p6, p7);
    S2(p1, p2); S2(p4, p5); S2(p7, p8);
    S2(p0, p3); S2(p5, p8); S2(p4, p7);
    S2(p3, p6); S2(p1, p4); S2(p2, p5);
    S2(p4, p7); S2(p4, p2); S2(p6, p4);
    S2(p4, p2);
    return p4;
}

__global__ __launch_bounds__(256, 4)
void MedianBlur_34505767256654_kernel(const float* __restrict__ in,
                                      float* __restrict__ out) {
    constexpr int W = 512;
    constexpr int H = 512;

    const int x0 = (blockIdx.x * 32 + threadIdx.x) * 4;   // first of 4 pixels
    const int y  = blockIdx.y * 8 + threadIdx.y;
    const long plane = blockIdx.z;                         // b*c plane index (24 planes)
    const long base = plane * (long)(H * W);

    const float* __restrict__ p = in + base;

    // r[row][col]: rows y-1..y+1, cols x0-1..x0+4 (zero-padded at borders)
    float r[3][6];

    #pragma unroll
    for (int i = 0; i < 3; ++i) {
        const int yy = y + i - 1;
        if (yy < 0 || yy >= H) {
            #pragma unroll
            for (int j = 0; j < 6; ++j) r[i][j] = 0.0f;
        } else {
            const float* __restrict__ row = p + yy * W;
            const float4 v = *reinterpret_cast<const float4*>(row + x0);
            r[i][1] = v.x; r[i][2] = v.y; r[i][3] = v.z; r[i][4] = v.w;
            r[i][0] = (x0 > 0)     ? __ldg(row + x0 - 1) : 0.0f;
            r[i][5] = (x0 + 4 < W) ? __ldg(row + x0 + 4) : 0.0f;
        }
    }

    float4 o;
    o.x = median9(r[0][0], r[0][1], r[0][2],
                  r[1][0], r[1][1], r[1][2],
                  r[2][0], r[2][1], r[2][2]);
    o.y = median9(r[0][1], r[0][2], r[0][3],
                  r[1][1], r[1][2], r[1][3],
                  r[2][1], r[2][2], r[2][3]);
    o.z = median9(r[0][2], r[0][3], r[0][4],
                  r[1][2], r[1][3], r[1][4],
                  r[2][2], r[2][3], r[2][4]);
    o.w = median9(r[0][3], r[0][4], r[0][5],
                  r[1][3], r[1][4], r[1][5],
                  r[2][3], r[2][4], r[2][5]);

    *reinterpret_cast<float4*>(out + base + (long)y * W + x0) = o;
}

extern "C" void kernel_launch(void* const* d_in, const int* in_sizes, int n_in,
                              void* d_out, int out_size) {
    (void)in_sizes; (void)n_in; (void)out_size;
    const float* x = (const float*)d_in[0];
    float* out = (float*)d_out;

    // (8,3,512,512): 24 planes of 512x512.
    dim3 block(32, 8, 1);                 // each thread: 4 pixels in x
    dim3 grid(512 / (32 * 4), 512 / 8, 24);
    MedianBlur_34505767256654_kernel<<<grid, block>>>(x, out);
}

// round 2
// speedup vs baseline: 1.1213x; 1.1213x over previous
#include <cuda_runtime.h>

// 3x3 median blur, zero padding, fp32 NCHW (8,3,512,512).
// Each thread: 4 adjacent x-pixels. Shared vertical column sorts +
// the med3(max-lows, med3-mids, min-highs) identity: 84 min/max ops
// per thread (21/pixel) vs ~30/pixel for the plain Smith network.

#define S2(a, b) { float _t = fminf(a, b); (b) = fmaxf(a, b); (a) = _t; }

__device__ __forceinline__ float med3(float x, float y, float z) {
    // median of 3: max(min(x,y), min(max(x,y), z))
    return fmaxf(fminf(x, y), fminf(fmaxf(x, y), z));
}

__device__ __forceinline__ float max3(float x, float y, float z) {
    return fmaxf(fmaxf(x, y), z);
}

__device__ __forceinline__ float min3(float x, float y, float z) {
    return fminf(fminf(x, y), z);
}

__global__ __launch_bounds__(256, 5)
void MedianBlur_34505767256654_kernel(const float* __restrict__ in,
                                      float* __restrict__ out) {
    constexpr int W = 512;
    constexpr int H = 512;

    const int x0 = (blockIdx.x * 32 + threadIdx.x) * 4;   // first of 4 pixels
    const int y  = blockIdx.y * 8 + threadIdx.y;
    const long base = (long)blockIdx.z * (long)(H * W);   // 24 planes

    const float* __restrict__ p = in + base;

    // r[row][col]: rows y-1..y+1, cols x0-1..x0+4 (zero-padded at borders)
    float r[3][6];

    #pragma unroll
    for (int i = 0; i < 3; ++i) {
        const int yy = y + i - 1;
        if (yy < 0 || yy >= H) {
            #pragma unroll
            for (int j = 0; j < 6; ++j) r[i][j] = 0.0f;
        } else {
            const float* __restrict__ row = p + yy * W;
            const float4 v = *reinterpret_cast<const float4*>(row + x0);
            r[i][1] = v.x; r[i][2] = v.y; r[i][3] = v.z; r[i][4] = v.w;
            r[i][0] = (x0 > 0)     ? __ldg(row + x0 - 1) : 0.0f;
            r[i][5] = (x0 + 4 < W) ? __ldg(row + x0 + 4) : 0.0f;
        }
    }

    // Vertical sort of each of the 6 columns (in place):
    // after this, r[0][j] = lo, r[1][j] = mid, r[2][j] = hi.
    #pragma unroll
    for (int j = 0; j < 6; ++j) {
        S2(r[0][j], r[1][j]);
        S2(r[1][j], r[2][j]);
        S2(r[0][j], r[1][j]);
    }

    // Per pixel k (columns k, k+1, k+2):
    // med9 = med3( max(lows), med3(mids), min(highs) )
    float o[4];
    #pragma unroll
    for (int k = 0; k < 4; ++k) {
        const float a = max3(r[0][k], r[0][k + 1], r[0][k + 2]);
        const float b = med3(r[1][k], r[1][k + 1], r[1][k + 2]);
        const float c = min3(r[2][k], r[2][k + 1], r[2][k + 2]);
        o[k] = med3(a, b, c);
    }

    float4 v;
    v.x = o[0]; v.y = o[1]; v.z = o[2]; v.w = o[3];
    *reinterpret_cast<float4*>(out + base + (long)y * W + x0) = v;
}

extern "C" void kernel_launch(void* const* d_in, const int* in_sizes, int n_in,
                              void* d_out, int out_size) {
    (void)in_sizes; (void)n_in; (void)out_size;
    const float* x = (const float*)d_in[0];
    float* out = (float*)d_out;

    dim3 block(32, 8, 1);                 // each thread: 4 pixels in x
    dim3 grid(512 / (32 * 4), 512 / 8, 24);
    MedianBlur_34505767256654_kernel<<<grid, block>>>(x, out);
}

// round 3
// speedup vs baseline: 1.3151x; 1.1729x over previous
#include <cuda_runtime.h>

// 3x3 median blur, zero padding, fp32 NCHW (8,3,512,512).
// Each thread: 2 rows x 8 cols. Column sorts shared across the 8 horizontal
// pixels AND across the 2 vertical windows (sort middle pair once, insert the
// outer row per window): 10 ops per column for two sorted triples.
// Merge per pixel: med3(max3(lows), med3(mids), min3(highs)) = 12 ops.
// Total ~18.25 min/max ops + ~1.0 loads per pixel.

__device__ __forceinline__ float med3(float a, float b, float c) {
    return fmaxf(fminf(a, b), fminf(fmaxf(a, b), c));
}
__device__ __forceinline__ float max3(float a, float b, float c) {
    return fmaxf(fmaxf(a, b), c);
}
__device__ __forceinline__ float min3(float a, float b, float c) {
    return fminf(fminf(a, b), c);
}

template <bool CHECK_Y>
__device__ __forceinline__ void tile2x8(const float* __restrict__ p,
                                        float* __restrict__ outp,
                                        int x0, int y0) {
    // Input window: rows y0-1 .. y0+2, cols x0-1 .. x0+8 (zero-padded).
    float v[4][10];
    const bool lx = (x0 > 0);
    const bool rx = (x0 + 8 < 512);

    #pragma unroll
    for (int i = 0; i < 4; ++i) {
        const int yy = y0 - 1 + i;
        if (CHECK_Y && (unsigned)yy >= 512u) {
            #pragma unroll
            for (int j = 0; j < 10; ++j) v[i][j] = 0.0f;
        } else {
            const float* __restrict__ row = p + yy * 512;
            const float4 a = *reinterpret_cast<const float4*>(row + x0);
            const float4 b = *reinterpret_cast<const float4*>(row + x0 + 4);
            v[i][1] = a.x; v[i][2] = a.y; v[i][3] = a.z; v[i][4] = a.w;
            v[i][5] = b.x; v[i][6] = b.y; v[i][7] = b.z; v[i][8] = b.w;
            v[i][0] = lx ? row[x0 - 1] : 0.0f;
            v[i][9] = rx ? row[x0 + 8] : 0.0f;
        }
    }

    // Per column: sorted triple of rows (0,1,2) -> A and rows (1,2,3) -> B,
    // sharing the (r1,r2) compare-exchange.
    float loA[10], miA[10], hiA[10];
    float loB[10], miB[10], hiB[10];
    #pragma unroll
    for (int j = 0; j < 10; ++j) {
        const float mn = fminf(v[1][j], v[2][j]);
        const float mx = fmaxf(v[1][j], v[2][j]);
        // window A: insert v[0][j] into sorted (mn, mx)
        const float a = v[0][j];
        loA[j] = fminf(a, mn);
        const float u = fmaxf(a, mn);
        miA[j] = fminf(u, mx);
        hiA[j] = fmaxf(u, mx);
        // window B: insert v[3][j] into sorted (mn, mx)
        const float d = v[3][j];
        loB[j] = fminf(d, mn);
        const float w = fmaxf(d, mn);
        miB[j] = fminf(w, mx);
        hiB[j] = fmaxf(w, mx);
    }

    // Merge: med9 = med3( max3(lows), med3(mids), min3(highs) )
    float oA[8], oB[8];
    #pragma unroll
    for (int k = 0; k < 8; ++k) {
        oA[k] = med3(max3(loA[k], loA[k + 1], loA[k + 2]),
                     med3(miA[k], miA[k + 1], miA[k + 2]),
                     min3(hiA[k], hiA[k + 1], hiA[k + 2]));
        oB[k] = med3(max3(loB[k], loB[k + 1], loB[k + 2]),
                     med3(miB[k], miB[k + 1], miB[k + 2]),
                     min3(hiB[k], hiB[k + 1], hiB[k + 2]));
    }

    float* __restrict__ rowA = outp + y0 * 512 + x0;
    float* __restrict__ rowB = rowA + 512;
    *reinterpret_cast<float4*>(rowA)     = make_float4(oA[0], oA[1], oA[2], oA[3]);
    *reinterpret_cast<float4*>(rowA + 4) = make_float4(oA[4], oA[5], oA[6], oA[7]);
    *reinterpret_cast<float4*>(rowB)     = make_float4(oB[0], oB[1], oB[2], oB[3]);
    *reinterpret_cast<float4*>(rowB + 4) = make_float4(oB[4], oB[5], oB[6], oB[7]);
}

__global__ __launch_bounds__(128, 6)
void MedianBlur_34505767256654_kernel(const float* __restrict__ in,
                                      float* __restrict__ out) {
    const int x0 = (blockIdx.x * 32 + threadIdx.x) * 8;   // 8 cols per thread
    const int y0 = (blockIdx.y * 4 + threadIdx.y) * 2;    // 2 rows per thread
    const int base = blockIdx.z * (512 * 512);            // 24 planes, fits int

    const float* __restrict__ p = in + base;
    float* __restrict__ o = out + base;

    // Only the top and bottom y-blocks touch the vertical border.
    if (blockIdx.y != 0 && blockIdx.y != 63) {
        tile2x8<false>(p, o, x0, y0);
    } else {
        tile2x8<true>(p, o, x0, y0);
    }
}

extern "C" void kernel_launch(void* const* d_in, const int* in_sizes, int n_in,
                              void* d_out, int out_size) {
    (void)in_sizes; (void)n_in; (void)out_size;
    const float* x = (const float*)d_in[0];
    float* out = (float*)d_out;

    dim3 block(32, 4, 1);                    // 128 threads, tile 256x8 per block
    dim3 grid(512 / 256, 512 / 8, 24);       // (2, 64, 24)
    MedianBlur_34505767256654_kernel<<<grid, block>>>(x, out);
}